// round 16
// baseline (speedup 1.0000x reference)
#include <cuda_runtime.h>
#include <cuda_fp16.h>
#include <cstdint>

#define SEQ    512
#define BATCH  64
#define DIM    512
#define MAXLEN 512
#define NWORDS (SEQ/32)

#define UTILE   32            // u rows per tile
#define KCHUNK  32            // fp32 k elems per chunk -> 64B fp16 row
#define NCHUNKS (DIM/KCHUNK)  // 16
#define NTILES  (64 * 16)     // (b, ut) tiles

// B: warp-private 64 s-rows x 64B = 4KB per stage, 3 stages per warp
#define WSTAGE     4096
#define NSTAGES    3
#define WREGION    (NSTAGES*WSTAGE)       // 12288 per warp
#define SM_TOTAL   (8*WREGION)            // 98304 -> 2 CTAs/SM

#define PREP_T   256
#define MMA_T    256          // 8 warps: 1(u) x 8(s), warp tile 32u x 64s
#define PGRID    296          // 2 x 148 persistent CTAs

#define CONVM_ITEMS (BATCH * NCHUNKS * SEQ * 4)   // 2097152
#define CONVW_ITEMS (NCHUNKS * 16 * 2 * 2 * 32)   // 32768 fragment uint4s

// ---- persistent device scratch ----
// gMc: [b][ck][s][64B fp16]
// gWfrag: [ck][ut][rg][ks][lane] uint4 -> exact mma A-fragment per thread
__device__ uint4 gMc[BATCH * NCHUNKS * SEQ * 4];   // 32 MB
__device__ uint4 gWfrag[CONVW_ITEMS];              // 512 KB
// Zero at module load; mea_mma's epilogue re-zeroes every word it consumes,
// so every invocation (correctness run + each graph replay) leaves it zeroed.
__device__ unsigned g_maskbits[BATCH * MAXLEN * NWORDS];

__device__ __forceinline__ uint32_t packh2(float x, float y) {
    __half2 h = __floats2half2_rn(x, y);
    return *(uint32_t*)&h;
}

// One kernel: mask-build + conv_M + conv_W(fragment pack), block-partitioned.
__global__ void prep_kernel(const int* __restrict__ eb,
                            const int* __restrict__ eu,
                            const int* __restrict__ ev, int E, int edgeBlocks,
                            const float* __restrict__ Mm,
                            const float* __restrict__ Wm) {
    const int bid = blockIdx.x;
    const int tid = threadIdx.x;

    if (bid < edgeBlocks) {                     // ---- build mask ----
        int i = bid * PREP_T + tid;
        if (i < E)
            atomicOr(&g_maskbits[(eb[i] * MAXLEN + eu[i]) * NWORDS + (ev[i] >> 5)],
                     1u << (ev[i] & 31));
        return;
    }
    int b2 = bid - edgeBlocks;
    if (b2 < CONVM_ITEMS / PREP_T) {            // ---- conv M -> fp16 64B rows ----
        int i = b2 * PREP_T + tid;
        int f4 = i & 3, s = (i >> 2) & 511, ck = (i >> 11) & 15, b = i >> 15;
        const float* src = &Mm[((size_t)s * BATCH + b) * DIM + ck * KCHUNK + f4 * 8];
        float4 v0 = *(const float4*)src;
        float4 v1 = *(const float4*)(src + 4);
        uint4 o;
        o.x = packh2(v0.x, v0.y); o.y = packh2(v0.z, v0.w);
        o.z = packh2(v1.x, v1.y); o.w = packh2(v1.z, v1.w);
        *(uint4*)((char*)gMc + ((size_t)((b * NCHUNKS + ck) * SEQ + s)) * 64 + f4 * 16) = o;
        return;
    }
    int b3 = b2 - CONVM_ITEMS / PREP_T;         // ---- conv W -> A fragments ----
    {
        int i = b3 * PREP_T + tid;
        if (i >= CONVW_ITEMS) return;
        int lane = i & 31, ks = (i >> 5) & 1, rg = (i >> 6) & 1,
            ut = (i >> 7) & 15, ck = i >> 11;
        int g = lane >> 2, tig = lane & 3;
        int u0 = ut * 32 + rg * 16 + g;
        int u1 = u0 + 8;
        int k0 = ck * KCHUNK + ks * 16 + tig * 2;
        float2 w00 = *(const float2*)&Wm[(size_t)u0 * DIM + k0];
        float2 w10 = *(const float2*)&Wm[(size_t)u1 * DIM + k0];
        float2 w01 = *(const float2*)&Wm[(size_t)u0 * DIM + k0 + 8];
        float2 w11 = *(const float2*)&Wm[(size_t)u1 * DIM + k0 + 8];
        uint4 o;
        o.x = packh2(w00.x, w00.y);
        o.y = packh2(w10.x, w10.y);
        o.z = packh2(w01.x, w01.y);
        o.w = packh2(w11.x, w11.y);
        gWfrag[i] = o;
    }
}

// ---------------- helpers ----------------
__device__ __forceinline__ uint32_t smem_u32(const void* p) {
    uint32_t a;
    asm("{ .reg .u64 t; cvta.to.shared.u64 t, %1; cvt.u32.u64 %0, t; }" : "=r"(a) : "l"(p));
    return a;
}
__device__ __forceinline__ uint32_t sw64(uint32_t off) { return off ^ ((off >> 3) & 0x30); }

__device__ __forceinline__ void ldsm_x4(uint32_t& r0, uint32_t& r1,
                                        uint32_t& r2, uint32_t& r3, uint32_t addr) {
    asm volatile("ldmatrix.sync.aligned.m8n8.x4.shared.b16 {%0,%1,%2,%3}, [%4];"
                 : "=r"(r0), "=r"(r1), "=r"(r2), "=r"(r3) : "r"(addr));
}

__device__ __forceinline__ void mma16816(float* d, const uint32_t* a,
                                         uint32_t b0, uint32_t b1) {
    asm volatile("mma.sync.aligned.m16n8k16.row.col.f32.f16.f16.f32 "
                 "{%0,%1,%2,%3}, {%4,%5,%6,%7}, {%8,%9}, {%0,%1,%2,%3};"
                 : "+f"(d[0]), "+f"(d[1]), "+f"(d[2]), "+f"(d[3])
                 : "r"(a[0]), "r"(a[1]), "r"(a[2]), "r"(a[3]), "r"(b0), "r"(b1));
}

__device__ __forceinline__ void cp16(uint32_t dst, const void* src) {
    asm volatile("cp.async.cg.shared.global [%0], [%1], 16;" :: "r"(dst), "l"(src));
}

// Warp-private B stage load: 64 rows x 64B, 8 cp16/lane + commit.
__device__ __forceinline__ void loadB_warp(uint32_t dstBase, const char* src, int lane) {
    #pragma unroll
    for (int it = 0; it < 8; it++) {
        int idx = it * 32 + lane;
        int r = idx >> 2, f4 = idx & 3;
        cp16(dstBase + sw64((uint32_t)(r * 64 + f4 * 16)), src + r * 64 + f4 * 16);
    }
    asm volatile("cp.async.commit_group;");
}

__device__ __forceinline__ void ldgA(uint4 fr[2][2], int ck, int ut, int lane) {
    const uint4* base = gWfrag + (((size_t)ck * 16 + ut) << 7) + lane;
    fr[0][0] = __ldg(base);       fr[0][1] = __ldg(base + 32);
    fr[1][0] = __ldg(base + 64);  fr[1][1] = __ldg(base + 96);
}

__device__ __forceinline__ void mma_chunk(float acc0[8][4], float acc1[8][4],
                                          uint4 A[2][2], uint32_t bBase,
                                          int b_kh, int xrB) {
    #pragma unroll
    for (int ks = 0; ks < 2; ks++) {
        const uint32_t bc = (uint32_t)((ks * 32 + b_kh) ^ xrB);
        const uint32_t* a0 = (const uint32_t*)&A[0][ks];
        const uint32_t* a1 = (const uint32_t*)&A[1][ks];
        #pragma unroll
        for (int np = 0; np < 4; np++) {
            uint32_t b0, b1, b2, b3;
            ldsm_x4(b0, b1, b2, b3, bBase + np * 1024 + bc);
            mma16816(acc0[2*np+0], a0, b0, b1);
            mma16816(acc0[2*np+1], a0, b2, b3);
            mma16816(acc1[2*np+0], a1, b0, b1);
            mma16816(acc1[2*np+1], a1, b2, b3);
        }
    }
}

#define WAIT1() asm volatile("cp.async.wait_group 1;" ::: "memory")
#define WAIT0() asm volatile("cp.async.wait_group 0;" ::: "memory")

__global__ __launch_bounds__(MMA_T, 2)
void mea_mma_kernel(float* __restrict__ out) {    // (BATCH, MAXLEN, SEQ)
    extern __shared__ char smem[];
    const uint32_t sb = smem_u32(smem);
    const int tid  = threadIdx.x;
    const int ws   = tid >> 5;      // warp = s-slice (64 cols), covers all 32 u
    const int lane = tid & 31;

    const uint32_t wBase = sb + ws * WREGION;

    // ldmatrix B per-lane address components (SW64, 64B rows) — loop invariant
    const int b_rowl = ((lane >> 4) << 3) + (lane & 7);
    const int b_kh   = ((lane >> 3) & 1) << 4;
    const int xrB    = ((b_rowl >> 1) & 3) << 4;
    const uint32_t bRowOff = (uint32_t)(b_rowl * 64);
    const int rl0 = lane >> 2;
    const int tig = lane & 3;
    float* red = (float*)smem;   // z: [0,256), am: [256,512)

    // ---------------- persistent tile loop ----------------
    #pragma unroll 1
    for (int t = blockIdx.x; t < NTILES; t += PGRID) {
        const int ut = t & 15;
        const int b  = t >> 4;
        const int utile = ut * UTILE;
        const char* srcB0 = (const char*)gMc
            + ((size_t)((b * NCHUNKS) * SEQ + ws * 64)) * 64;   // + ck*SEQ*64

        float acc0[8][4], acc1[8][4];
        #pragma unroll
        for (int nt = 0; nt < 8; nt++)
            #pragma unroll
            for (int j = 0; j < 4; j++) { acc0[nt][j] = 0.f; acc1[nt][j] = 0.f; }

        uint4 Aeven[2][2], Aodd[2][2];

        loadB_warp(wBase + 0,      srcB0 + (size_t)0 * SEQ * 64, lane);
        loadB_warp(wBase + WSTAGE, srcB0 + (size_t)1 * SEQ * 64, lane);
        ldgA(Aeven, 0, ut, lane);

        uint32_t cOff = 0, pOff = 2 * WSTAGE;

        #pragma unroll 1
        for (int ck2 = 0; ck2 < NCHUNKS; ck2 += 2) {
            // ---- even chunk ck2 ----
            WAIT1(); __syncwarp();
            if (ck2 + 2 < NCHUNKS)
                loadB_warp(wBase + pOff, srcB0 + (size_t)(ck2 + 2) * SEQ * 64, lane);
            ldgA(Aodd, ck2 + 1, ut, lane);
            mma_chunk(acc0, acc1, Aeven, wBase + cOff + bRowOff, b_kh, xrB);
            cOff += WSTAGE; if (cOff == WREGION) cOff = 0;
            pOff += WSTAGE; if (pOff == WREGION) pOff = 0;

            // ---- odd chunk ck2+1 ----
            if (ck2 + 1 == NCHUNKS - 1) { WAIT0(); } else { WAIT1(); }
            __syncwarp();
            if (ck2 + 3 < NCHUNKS)
                loadB_warp(wBase + pOff, srcB0 + (size_t)(ck2 + 3) * SEQ * 64, lane);
            if (ck2 + 2 < NCHUNKS)
                ldgA(Aeven, ck2 + 2, ut, lane);
            mma_chunk(acc0, acc1, Aodd, wBase + cOff + bRowOff, b_kh, xrB);
            cOff += WSTAGE; if (cOff == WREGION) cOff = 0;
            pOff += WSTAGE; if (pOff == WREGION) pOff = 0;
        }
        __syncthreads();   // all warps done with stages before red-buffer reuse

        // ---------------- epilogue ----------------
        int rows[4];
        rows[0] = rl0; rows[1] = rl0 + 8; rows[2] = rl0 + 16; rows[3] = rl0 + 24;

        unsigned wmask[4][2];
        #pragma unroll
        for (int j = 0; j < 4; j++) {
            int r = b * MAXLEN + utile + rows[j];
            wmask[j][0] = g_maskbits[r * NWORDS + ws * 2 + 0];
            wmask[j][1] = g_maskbits[r * NWORDS + ws * 2 + 1];
        }
        // Consume-and-clear: each (row, word) owned by exactly one warp's tig==0
        // lane. Leaves the bitmap all-zero for the next invocation.
        if (tig == 0) {
            #pragma unroll
            for (int j = 0; j < 4; j++) {
                int r = b * MAXLEN + utile + rows[j];
                g_maskbits[r * NWORDS + ws * 2 + 0] = 0u;
                g_maskbits[r * NWORDS + ws * 2 + 1] = 0u;
            }
        }

        float zz[4] = {0.f, 0.f, 0.f, 0.f}, aa[4] = {0.f, 0.f, 0.f, 0.f};
        #pragma unroll
        for (int rg = 0; rg < 2; rg++) {
            float (*acc)[4] = rg ? acc1 : acc0;
            #pragma unroll
            for (int nt = 0; nt < 8; nt++) {
                const int q   = nt >> 2;
                const int bit = (nt & 3) * 8 + 2 * tig;
                float e0 = __expf(acc[nt][0]);
                float e1 = __expf(acc[nt][1]);
                float e2 = __expf(acc[nt][2]);
                float e3 = __expf(acc[nt][3]);
                acc[nt][0] = e0; acc[nt][1] = e1; acc[nt][2] = e2; acc[nt][3] = e3;
                zz[2*rg]   += e0 + e1;
                zz[2*rg+1] += e2 + e3;
                if ((wmask[2*rg][q]   >> bit)       & 1u) aa[2*rg]   += e0;
                if ((wmask[2*rg][q]   >> (bit + 1)) & 1u) aa[2*rg]   += e1;
                if ((wmask[2*rg+1][q] >> bit)       & 1u) aa[2*rg+1] += e2;
                if ((wmask[2*rg+1][q] >> (bit + 1)) & 1u) aa[2*rg+1] += e3;
            }
        }
        #pragma unroll
        for (int o = 1; o <= 2; o <<= 1) {
            #pragma unroll
            for (int j = 0; j < 4; j++) {
                zz[j] += __shfl_xor_sync(0xffffffffu, zz[j], o);
                aa[j] += __shfl_xor_sync(0xffffffffu, aa[j], o);
            }
        }

        if (tig == 0) {
            #pragma unroll
            for (int j = 0; j < 4; j++) {
                red[ws * 32 + rows[j]]       = zz[j];
                red[256 + ws * 32 + rows[j]] = aa[j];
            }
        }
        __syncthreads();

        float inv[4];
        #pragma unroll
        for (int j = 0; j < 4; j++) {
            float zs = 0.f, as = 0.f;
            #pragma unroll
            for (int w = 0; w < 8; w++) {
                zs += red[w * 32 + rows[j]];
                as += red[256 + w * 32 + rows[j]];
            }
            inv[j] = 1.0f / (as + 1e-10f * (zs - as));
        }

        #pragma unroll
        for (int rg = 0; rg < 2; rg++) {
            float (*acc)[4] = rg ? acc1 : acc0;
            const int r0 = b * MAXLEN + utile + rows[2*rg];
            const int r1 = b * MAXLEN + utile + rows[2*rg+1];
            #pragma unroll
            for (int nt = 0; nt < 8; nt++) {
                const int q   = nt >> 2;
                const int bit = (nt & 3) * 8 + 2 * tig;
                const int sc  = ws * 64 + nt * 8 + 2 * tig;
                float2 v0, v1;
                v0.x = ((wmask[2*rg][q]   >> bit)       & 1u) ? acc[nt][0] * inv[2*rg]   : 0.f;
                v0.y = ((wmask[2*rg][q]   >> (bit + 1)) & 1u) ? acc[nt][1] * inv[2*rg]   : 0.f;
                v1.x = ((wmask[2*rg+1][q] >> bit)       & 1u) ? acc[nt][2] * inv[2*rg+1] : 0.f;
                v1.y = ((wmask[2*rg+1][q] >> (bit + 1)) & 1u) ? acc[nt][3] * inv[2*rg+1] : 0.f;
                *(float2*)&out[(size_t)r0 * SEQ + sc] = v0;
                *(float2*)&out[(size_t)r1 * SEQ + sc] = v1;
            }
        }
        __syncthreads();   // red buffer consumed before next tile's stage loads
    }
}

extern "C" void kernel_launch(void* const* d_in, const int* in_sizes, int n_in,
                              void* d_out, int out_size) {
    const float* M  = (const float*)d_in[0];
    const float* W  = (const float*)d_in[1];
    const int*   eb = (const int*)d_in[3];
    const int*   eu = (const int*)d_in[4];
    const int*   ev = (const int*)d_in[5];
    const int    E  = in_sizes[3];
    float* out = (float*)d_out;

    cudaFuncSetAttribute(mea_mma_kernel,
                         cudaFuncAttributeMaxDynamicSharedMemorySize, SM_TOTAL);

    const int edgeBlocks = (E + PREP_T - 1) / PREP_T;
    const int prepBlocks = edgeBlocks + CONVM_ITEMS / PREP_T
                         + (CONVW_ITEMS + PREP_T - 1) / PREP_T;
    prep_kernel<<<prepBlocks, PREP_T>>>(eb, eu, ev, E, edgeBlocks, M, W);
    mea_mma_kernel<<<PGRID, MMA_T, SM_TOTAL>>>(out);
}